// round 14
// baseline (speedup 1.0000x reference)
#include <cuda_runtime.h>
#include <cuda_bf16.h>
#include <math_constants.h>

// Problem constants
#define NPTS    8192
#define KCOMP   64
#define NBINS   256
#define MBLK    1024         // main blocks
#define WPB     8            // warps (j's) per main block
#define HSTRIDE 257          // padded stride for warp-private hists (bank-conflict-free)

// KDE: bw = 0.5*128/8192 = 2^-7 exactly  ->  exp(-8192*d^2) = exp2(CKDE*d^2)
#define LOG2E 1.4426950408889634
__device__ __constant__ float CKDE = (float)(-8192.0 * LOG2E);
__device__ __constant__ float NORM = (float)(1.0 / (2.5066282746310002 * 0.0078125 * 8192.0));
// ex2.ftz -> exact 0 for |d| > 0.10327. Fixed bins: width 0.052, +/-2-bin window
// covers +/-0.104 > R. Edge clamping only EXTENDS windows -> correct for any input.
#define BIN_LO  (-6.656f)
#define BIN_IW  (19.230769230769230769f)   // 1/0.052

// Scratch (device globals — no allocation allowed)
__device__ __align__(16) float g_xs[NPTS];   // x counting-sorted by bin
__device__ __align__(16) int2  g_win[NPTS];  // per-j candidate window [c0,c1)
__device__ float g_coef[KCOMP];              // w_k / sqrt(2*pi*var_k)
__device__ float g_a[KCOMP];                 // -0.5*log2e / var_k
__device__ float g_bsum[MBLK];
__device__ int   g_ticket = 0;               // self-resets each call

__device__ __forceinline__ float ex2(float x) {
    float r;
    asm("ex2.approx.ftz.f32 %0, %1;" : "=f"(r) : "f"(x));
    return r;
}

__device__ __forceinline__ int bin_of(float v) {
    int b = (int)floorf((v - BIN_LO) * BIN_IW);
    return max(min(b, NBINS - 1), 0);
}

// ---------------------------------------------------------------------------
// 1) Prep (R10-proven): counting sort with warp-private histograms; the
//    atomicAdd RETURN VALUE is the element's intra-(warp,bin) rank -> no
//    cursor pass, near-zero contention. NEW: per-j window (c0,c1) is written
//    at scatter time (bin + bs[] already in hand) so main's warps skip the
//    serial  xj -> bin -> binstart  dependency chain entirely.
// ---------------------------------------------------------------------------
__global__ __launch_bounds__(1024) void gmm_prep(const float* __restrict__ x,
                                                 const float* __restrict__ wl,
                                                 const float* __restrict__ lv) {
    __shared__ int h[HSTRIDE * 32];     // h[bin + HSTRIDE*warp]
    __shared__ int tot[NBINS];
    __shared__ int bs[NBINS + 1];

    const int t = threadIdx.x, lane = t & 31, w = t >> 5;

    #pragma unroll
    for (int i = t; i < HSTRIDE * 32; i += 1024) h[i] = 0;
    __syncthreads();

    // load 8 elements/thread; build hists; rank = atomicAdd return
    float xv[8];
    int   bidx[8], rank[8];
    #pragma unroll
    for (int e = 0; e < 8; e++) {
        float v = x[t + e * 1024];
        xv[e]   = v;
        int b   = bin_of(v);
        bidx[e] = b;
        rank[e] = atomicAdd(&h[b + HSTRIDE * w], 1);
    }
    __syncthreads();

    // per-bin exclusive scan across the 32 warps (thread-per-bin, in place)
    if (t < NBINS) {
        int run = 0;
        #pragma unroll
        for (int k = 0; k < 32; k++) {
            int idx = t + HSTRIDE * k;
            int v = h[idx];
            h[idx] = run;
            run += v;
        }
        tot[t] = run;
    }
    __syncthreads();

    // warp 0: exclusive scan of 256 bin totals (8/lane serial + shfl scan)
    if (t < 32) {
        int v[8], p[8], run = 0;
        #pragma unroll
        for (int k = 0; k < 8; k++) {
            v[k] = tot[t * 8 + k];
            p[k] = run;
            run += v[k];
        }
        int incl = run;
        #pragma unroll
        for (int o = 1; o < 32; o <<= 1) {
            int u = __shfl_up_sync(0xffffffffu, incl, o);
            if (lane >= o) incl += u;
        }
        int excl = incl - run;
        #pragma unroll
        for (int k = 0; k < 8; k++) bs[t * 8 + k] = excl + p[k];
        if (t == 31) bs[NBINS] = incl;   // == NPTS
    }
    __syncthreads();

    // scatter: pos = binstart + warp-prefix + rank (unique by construction).
    // Also emit this element's candidate window — it lands at sorted index pos.
    #pragma unroll
    for (int e = 0; e < 8; e++) {
        int b   = bidx[e];
        int pos = bs[b] + h[b + HSTRIDE * w] + rank[e];
        g_xs[pos]  = xv[e];
        g_win[pos] = make_int2(bs[max(b - 2, 0)], bs[min(b + 3, NBINS)]);
    }

    // softmax + per-component constants (direct global reads -> race-free)
    if (t < KCOMP) {
        float m = -CUDART_INF_F;
        #pragma unroll
        for (int i = 0; i < KCOMP; i++) m = fmaxf(m, __ldg(&wl[i]));
        float ssum = 0.0f;
        #pragma unroll
        for (int i = 0; i < KCOMP; i++) ssum += __expf(__ldg(&wl[i]) - m);
        float wgt = __expf(__ldg(&wl[t]) - m) / ssum;
        float var = __expf(lv[t]);
        g_coef[t] = wgt * rsqrtf(6.283185307179586f * var);
        g_a[t]    = (float)(-0.5 * LOG2E) / var;
    }
}

// ---------------------------------------------------------------------------
// 2) Main (R10 structure, best measured): one warp per sorted j. Window comes
//    from g_win[j] (one independent 8B load; __ldg legal — written by the
//    PREVIOUS kernel). Single folded butterfly reduction. unroll 8 for MLP.
// ---------------------------------------------------------------------------
__global__ __launch_bounds__(256) void gmm_main(const float* __restrict__ means,
                                                float* __restrict__ out) {
    __shared__ float smn[KCOMP], scf[KCOMP], sa[KCOMP];
    __shared__ float wsum[WPB];
    __shared__ float rs[256];
    __shared__ int   s_last;

    int tid = threadIdx.x, lane = tid & 31, w = tid >> 5;
    if (tid < KCOMP) {
        smn[tid] = means[tid];
        scf[tid] = g_coef[tid];
        sa[tid]  = g_a[tid];
    }
    __syncthreads();

    const int  j   = blockIdx.x * WPB + w;
    const int2 win = __ldg(&g_win[j]);       // independent of xj load
    const float xj = __ldg(&g_xs[j]);

    const float ck = CKDE;
    float acc = 0.0f;
    #pragma unroll 8
    for (int i = win.x + lane; i < win.y; i += 32) {
        float d = xj - __ldg(&g_xs[i]);      // Sterbenz-exact for close pairs
        acc += ex2(ck * d * d);
    }

    // mixture pdf partial: 2 components per lane
    float d1 = xj - smn[lane];
    float mixp = scf[lane] * ex2(sa[lane] * d1 * d1);
    float d2 = xj - smn[lane + 32];
    mixp += scf[lane + 32] * ex2(sa[lane + 32] * d2 * d2);

    // fold before reducing: sum_lanes(mixp - NORM*acc) = mixture_j - data_j
    float t = mixp - NORM * acc;
    #pragma unroll
    for (int o = 16; o > 0; o >>= 1) t += __shfl_xor_sync(0xffffffffu, t, o);
    if (lane == 0) wsum[w] = t * t;
    __syncthreads();

    if (tid == 0) {
        float v = 0.0f;
        #pragma unroll
        for (int p = 0; p < WPB; p++) v += wsum[p];
        g_bsum[blockIdx.x] = v;
        __threadfence();
        int tk = atomicAdd(&g_ticket, 1);
        s_last = (tk == MBLK - 1);
    }
    __syncthreads();

    if (s_last) {
        __threadfence();                     // acquire: order reads after ticket
        float v = 0.0f;
        #pragma unroll
        for (int q = 0; q < MBLK / 256; q++) v += g_bsum[tid + q * 256];
        rs[tid] = v;
        __syncthreads();
        #pragma unroll
        for (int off = 128; off > 0; off >>= 1) {
            if (tid < off) rs[tid] += rs[tid + off];
            __syncthreads();
        }
        if (tid == 0) {
            out[0] = rs[0];
            g_ticket = 0;   // reset for next graph replay
        }
    }
}

extern "C" void kernel_launch(void* const* d_in, const int* in_sizes, int n_in,
                              void* d_out, int out_size) {
    const float* x  = (const float*)d_in[0];  // [8192]
    const float* wl = (const float*)d_in[1];  // [64] weight_logits
    const float* mu = (const float*)d_in[2];  // [64] means
    const float* lv = (const float*)d_in[3];  // [64] log_vars
    float* out = (float*)d_out;

    gmm_prep<<<1, 1024>>>(x, wl, lv);
    gmm_main<<<MBLK, 256>>>(mu, out);
}

// round 15
// speedup vs baseline: 1.3636x; 1.3636x over previous
#include <cuda_runtime.h>
#include <cuda_bf16.h>
#include <math_constants.h>

// Problem constants
#define NPTS    8192
#define KCOMP   64
#define NBINS   256
#define MBLK    1024         // main blocks
#define WPB     8            // warps (j's) per main block
#define HSTRIDE 257          // padded stride for warp-private hists (bank-conflict-free)

// KDE: bw = 0.5*128/8192 = 2^-7 exactly  ->  exp(-8192*d^2) = exp2(CKDE*d^2)
#define LOG2E 1.4426950408889634
__device__ __constant__ float CKDE = (float)(-8192.0 * LOG2E);
__device__ __constant__ float NORM = (float)(1.0 / (2.5066282746310002 * 0.0078125 * 8192.0));
// ex2.ftz -> exact 0 for |d| > 0.10327. Fixed bins: width 0.052, +/-2-bin window
// covers +/-0.104 > R. Edge clamping only EXTENDS windows -> correct for any input.
#define BIN_LO  (-6.656f)
#define BIN_IW  (19.230769230769230769f)   // 1/0.052

// Scratch (device globals — no allocation allowed)
__device__ __align__(16) float g_xs[NPTS];   // x counting-sorted by bin
__device__ int   g_binstart[NBINS + 1];      // exclusive-scan offsets; [NBINS] = NPTS
__device__ float g_bsum[MBLK];
__device__ int   g_ticket = 0;               // self-resets each call

__device__ __forceinline__ float ex2(float x) {
    float r;
    asm("ex2.approx.ftz.f32 %0, %1;" : "=f"(r) : "f"(x));
    return r;
}

__device__ __forceinline__ int bin_of(float v) {
    int b = (int)floorf((v - BIN_LO) * BIN_IW);
    return max(min(b, NBINS - 1), 0);
}

// ---------------------------------------------------------------------------
// 1) Prep (exact R10 sort, softmax removed — main computes it while waiting):
//    counting sort with warp-private histograms; atomicAdd return value is the
//    intra-(warp,bin) rank -> no cursor pass, near-zero contention.
// ---------------------------------------------------------------------------
__global__ __launch_bounds__(1024) void gmm_prep(const float* __restrict__ x) {
    __shared__ int h[HSTRIDE * 32];     // h[bin + HSTRIDE*warp]
    __shared__ int tot[NBINS];
    __shared__ int bs[NBINS + 1];

    const int t = threadIdx.x, lane = t & 31, w = t >> 5;

    #pragma unroll
    for (int i = t; i < HSTRIDE * 32; i += 1024) h[i] = 0;
    __syncthreads();

    float xv[8];
    int   bidx[8], rank[8];
    #pragma unroll
    for (int e = 0; e < 8; e++) {
        float v = x[t + e * 1024];
        xv[e]   = v;
        int b   = bin_of(v);
        bidx[e] = b;
        rank[e] = atomicAdd(&h[b + HSTRIDE * w], 1);
    }
    __syncthreads();

    // per-bin exclusive scan across the 32 warps (thread-per-bin, in place)
    if (t < NBINS) {
        int run = 0;
        #pragma unroll
        for (int k = 0; k < 32; k++) {
            int idx = t + HSTRIDE * k;
            int v = h[idx];
            h[idx] = run;
            run += v;
        }
        tot[t] = run;
    }
    __syncthreads();

    // warp 0: exclusive scan of 256 bin totals (8/lane serial + shfl scan)
    if (t < 32) {
        int v[8], p[8], run = 0;
        #pragma unroll
        for (int k = 0; k < 8; k++) {
            v[k] = tot[t * 8 + k];
            p[k] = run;
            run += v[k];
        }
        int incl = run;
        #pragma unroll
        for (int o = 1; o < 32; o <<= 1) {
            int u = __shfl_up_sync(0xffffffffu, incl, o);
            if (lane >= o) incl += u;
        }
        int excl = incl - run;
        #pragma unroll
        for (int k = 0; k < 8; k++) bs[t * 8 + k] = excl + p[k];
        if (t == 31) bs[NBINS] = incl;   // == NPTS
    }
    __syncthreads();

    // scatter: pos = binstart + warp-prefix + rank (unique by construction)
    #pragma unroll
    for (int e = 0; e < 8; e++) {
        int pos = bs[bidx[e]] + h[bidx[e] + HSTRIDE * w] + rank[e];
        g_xs[pos] = xv[e];
    }
    if (t <= NBINS) g_binstart[t] = bs[t];
}

// ---------------------------------------------------------------------------
// 2) Main, launched with PDL: starts WHILE prep runs. Pre-sync: cooperative
//    softmax constants (wl/lv/mu only) + mixture partial from ORIGINAL x[j]
//    (sum over j is permutation-invariant). Then cudaGridDependencySynchronize
//    and the KDE window loop over prep's sorted output (plain coherent loads).
// ---------------------------------------------------------------------------
__global__ __launch_bounds__(256) void gmm_main(const float* __restrict__ x,
                                                const float* __restrict__ wl,
                                                const float* __restrict__ mu,
                                                const float* __restrict__ lv,
                                                float* __restrict__ out) {
    __shared__ float smn[KCOMP], scf[KCOMP], sa[KCOMP];
    __shared__ float redv[4];
    __shared__ float wsum[WPB];
    __shared__ float rs[256];
    __shared__ int   s_last;

    const int tid = threadIdx.x, lane = tid & 31, w = tid >> 5;

    // ---- cooperative softmax constants (overlaps prep execution) ----
    float l = 0.0f, e = 0.0f;
    if (tid < KCOMP) l = __ldg(&wl[tid]);
    if (w < 2) {
        float m = l;
        #pragma unroll
        for (int o = 16; o > 0; o >>= 1) m = fmaxf(m, __shfl_xor_sync(0xffffffffu, m, o));
        if (lane == 0) redv[w] = m;
    }
    __syncthreads();
    {
        float m = fmaxf(redv[0], redv[1]);
        if (w < 2) {
            e = __expf(l - m);
            float s = e;
            #pragma unroll
            for (int o = 16; o > 0; o >>= 1) s += __shfl_xor_sync(0xffffffffu, s, o);
            if (lane == 0) redv[2 + w] = s;
        }
    }
    __syncthreads();
    if (tid < KCOMP) {
        float S   = redv[2] + redv[3];
        float wgt = e / S;
        float var = __expf(__ldg(&lv[tid]));
        smn[tid] = __ldg(&mu[tid]);
        scf[tid] = wgt * rsqrtf(6.283185307179586f * var);
        sa[tid]  = (float)(-0.5 * LOG2E) / var;
    }
    __syncthreads();

    // j from ORIGINAL x: no prep dependency; const input -> __ldg legal
    const int j = blockIdx.x * WPB + w;
    const float xj = __ldg(&x[j]);

    // mixture pdf partial (2 comps/lane) — still pre-sync
    float d1 = xj - smn[lane];
    float mixp = scf[lane] * ex2(sa[lane] * d1 * d1);
    float d2 = xj - smn[lane + 32];
    mixp += scf[lane + 32] * ex2(sa[lane + 32] * d2 * d2);

    // ---- wait for prep's writes (PDL dependency), then KDE ----
    cudaGridDependencySynchronize();

    int b  = bin_of(xj);
    int c0 = g_binstart[max(b - 2, 0)];      // plain coherent loads (concurrent
    int c1 = g_binstart[min(b + 3, NBINS)];  // producer kernel -> no __ldg)

    const float ck = CKDE;
    float acc = 0.0f;
    #pragma unroll 4
    for (int i = c0 + lane; i < c1; i += 32) {
        float d = xj - g_xs[i];              // Sterbenz-exact for close pairs
        acc += ex2(ck * d * d);
    }

    // fold before reducing: sum_lanes(mixp - NORM*acc) = mixture_j - data_j
    float t = mixp - NORM * acc;
    #pragma unroll
    for (int o = 16; o > 0; o >>= 1) t += __shfl_xor_sync(0xffffffffu, t, o);
    if (lane == 0) wsum[w] = t * t;
    __syncthreads();

    if (tid == 0) {
        float v = 0.0f;
        #pragma unroll
        for (int p = 0; p < WPB; p++) v += wsum[p];
        g_bsum[blockIdx.x] = v;
        __threadfence();
        int tk = atomicAdd(&g_ticket, 1);
        s_last = (tk == MBLK - 1);
    }
    __syncthreads();

    if (s_last) {
        __threadfence();                     // acquire: order reads after ticket
        float v = 0.0f;
        #pragma unroll
        for (int q = 0; q < MBLK / 256; q++) v += g_bsum[tid + q * 256];
        rs[tid] = v;
        __syncthreads();
        #pragma unroll
        for (int off = 128; off > 0; off >>= 1) {
            if (tid < off) rs[tid] += rs[tid + off];
            __syncthreads();
        }
        if (tid == 0) {
            out[0] = rs[0];
            g_ticket = 0;   // reset for next graph replay
        }
    }
}

extern "C" void kernel_launch(void* const* d_in, const int* in_sizes, int n_in,
                              void* d_out, int out_size) {
    const float* x  = (const float*)d_in[0];  // [8192]
    const float* wl = (const float*)d_in[1];  // [64] weight_logits
    const float* mu = (const float*)d_in[2];  // [64] means
    const float* lv = (const float*)d_in[3];  // [64] log_vars
    float* out = (float*)d_out;

    gmm_prep<<<1, 1024>>>(x);

    // PDL: main may begin before prep completes; it synchronizes in-kernel
    // via cudaGridDependencySynchronize() before reading prep's outputs.
    cudaLaunchConfig_t cfg = {};
    cfg.gridDim  = dim3(MBLK);
    cfg.blockDim = dim3(256);
    cfg.dynamicSmemBytes = 0;
    cfg.stream = 0;                          // same (legacy) stream as <<<>>>
    cudaLaunchAttribute attr[1];
    attr[0].id = cudaLaunchAttributeProgrammaticStreamSerialization;
    attr[0].val.programmaticStreamSerializationAllowed = 1;
    cfg.attrs = attr;
    cfg.numAttrs = 1;
    cudaLaunchKernelEx(&cfg, gmm_main, x, wl, mu, lv, out);
}